// round 2
// baseline (speedup 1.0000x reference)
#include <cuda_runtime.h>
#include <math.h>

// Problem constants
#define NB 2
#define NS 512
#define ND 256
#define NH 8
#define NA 32
#define NBS (NB*NS)          // 1024
#define B_CONSTF 0.9f
#define EPSF 1e-10f
#define SCALEF 0.0625f       // 1/sqrt(256)

// ---------------- device scratch ----------------
__device__ float g_q [NBS*ND];        // 1 MB
__device__ float g_kv[NBS*2*ND];      // 2 MB  (k: cols 0..255, v: cols 256..511)
__device__ float g_e [NBS*ND];        // 1 MB
__device__ float g_vmin   [NB*ND];
__device__ float g_nscale [NB*ND];
__device__ float g_unscale[NB*ND];
__device__ float g_p   [ND];
__device__ float g_invp[ND];

// ---------------- f32x2 packed helpers ----------------
__device__ __forceinline__ unsigned long long f2pack(float lo, float hi) {
    unsigned long long r;
    asm("mov.b64 %0, {%1, %2};" : "=l"(r) : "f"(lo), "f"(hi));
    return r;
}
__device__ __forceinline__ void f2unpack(unsigned long long v, float& lo, float& hi) {
    asm("mov.b64 {%0, %1}, %2;" : "=f"(lo), "=f"(hi) : "l"(v));
}
__device__ __forceinline__ unsigned long long f2fma(unsigned long long a,
                                                    unsigned long long b,
                                                    unsigned long long c) {
    unsigned long long d;
    asm("fma.rn.f32x2 %0, %1, %2, %3;" : "=l"(d) : "l"(a), "l"(b), "l"(c));
    return d;
}

// ---------------- GEMM: C[M,N] = A[M,K] @ B[N,K]^T, f32x2 dual-issue ----------------
// 64x64 block tile, BK=16, 128 threads, 8m x 4n per thread (m packed in f32x2 pairs).
// Column split: col < splitN -> C0 (ld0), else C1 (ld1) at col-splitN.
__global__ void __launch_bounds__(128) gemm_f32x2_kernel(
    const float* __restrict__ A, const float* __restrict__ Bm,
    float* __restrict__ C0, float* __restrict__ C1,
    int K, int splitN, int ld0, int ld1)
{
    __shared__ float As[16][64];   // k-major: As[kk][m]
    __shared__ float Bs[16][64];   // k-major: Bs[kk][n]
    const int tid = threadIdx.x;
    const int tx  = tid & 15;      // n group (4 cols)
    const int tm  = tid >> 4;      // m group (8 rows)
    const int bm  = blockIdx.y * 64;
    const int bn  = blockIdx.x * 64;

    unsigned long long acc[4][4];  // [n][m-pair]
    #pragma unroll
    for (int j = 0; j < 4; j++)
        #pragma unroll
        for (int i = 0; i < 4; i++) acc[j][i] = 0ULL;

    const int lrow = tid & 63;
    const int lkg  = tid >> 6;     // 0..1

    for (int k0 = 0; k0 < K; k0 += 16) {
        #pragma unroll
        for (int r = 0; r < 2; r++) {
            int kg = lkg * 2 + r;  // 0..3
            float4 a4 = *(const float4*)&A [(size_t)(bm + lrow) * K + k0 + kg * 4];
            As[kg*4+0][lrow] = a4.x; As[kg*4+1][lrow] = a4.y;
            As[kg*4+2][lrow] = a4.z; As[kg*4+3][lrow] = a4.w;
            float4 b4 = *(const float4*)&Bm[(size_t)(bn + lrow) * K + k0 + kg * 4];
            Bs[kg*4+0][lrow] = b4.x; Bs[kg*4+1][lrow] = b4.y;
            Bs[kg*4+2][lrow] = b4.z; Bs[kg*4+3][lrow] = b4.w;
        }
        __syncthreads();
        #pragma unroll
        for (int kk = 0; kk < 16; kk++) {
            ulonglong2 t0 = *(const ulonglong2*)&As[kk][tm*8];
            ulonglong2 t1 = *(const ulonglong2*)&As[kk][tm*8 + 4];
            unsigned long long ra0 = t0.x, ra1 = t0.y, ra2 = t1.x, ra3 = t1.y;
            #pragma unroll
            for (int j = 0; j < 4; j++) {
                float rbf = Bs[kk][tx*4 + j];
                unsigned long long rb2 = f2pack(rbf, rbf);
                acc[j][0] = f2fma(rb2, ra0, acc[j][0]);
                acc[j][1] = f2fma(rb2, ra1, acc[j][1]);
                acc[j][2] = f2fma(rb2, ra2, acc[j][2]);
                acc[j][3] = f2fma(rb2, ra3, acc[j][3]);
            }
        }
        __syncthreads();
    }

    #pragma unroll
    for (int j = 0; j < 4; j++) {
        int col = bn + tx*4 + j;
        float* Cp; int ldc, c;
        if (col < splitN) { Cp = C0; ldc = ld0; c = col; }
        else              { Cp = C1; ldc = ld1; c = col - splitN; }
        #pragma unroll
        for (int i = 0; i < 4; i++) {
            float f0, f1;
            f2unpack(acc[j][i], f0, f1);
            int row = bm + tm*8 + 2*i;
            Cp[(size_t)row * ldc + c]       = f0;
            Cp[(size_t)(row+1) * ldc + c]   = f1;
        }
    }
}

// ---------------- per-(b,d) min/max over S + p / invp ----------------
__global__ void vstats_kernel(const float* __restrict__ p_param) {
    __shared__ float smn[4][256];
    __shared__ float smx[4][256];
    const int b  = blockIdx.x;
    const int d  = threadIdx.x & 255;
    const int sl = threadIdx.x >> 8;

    float vmn = 1e30f, vmx = -1e30f;
    const float* base = g_kv + (size_t)(b * NS + sl * 128) * (2 * ND) + ND + d;
    #pragma unroll 8
    for (int s = 0; s < 128; s++) {
        float v = base[s * (2 * ND)];
        vmn = fminf(vmn, v);
        vmx = fmaxf(vmx, v);
    }
    smn[sl][d] = vmn;
    smx[sl][d] = vmx;
    __syncthreads();
    if (sl == 0) {
        vmn = fminf(fminf(smn[0][d], smn[1][d]), fminf(smn[2][d], smn[3][d]));
        vmx = fmaxf(fmaxf(smx[0][d], smx[1][d]), fmaxf(smx[2][d], smx[3][d]));
        float range = vmx - vmn + EPSF;
        g_vmin   [b*ND + d] = vmn;
        g_nscale [b*ND + d] = (1.0f - B_CONSTF) / range;
        g_unscale[b*ND + d] = range / (1.0f - B_CONSTF);
        if (b == 0) {
            float pp = p_param[d];
            float p  = 50000.0f * tanhf(0.005f * pp) + 1.0f;
            if (p == 0.0f) p = 1e-4f;
            g_p   [d] = p;
            g_invp[d] = 1.0f / p;
        }
    }
}

// ---------------- attention: power-mean softmax, f32x2 inner loop ----------------
// grid = 128 blocks: b(1b) x h(3b) x qtile(3b); 256 threads = 64 queries x 4 key-slices
// smem: Ks[512][32] + Vs[512][32] = 128 KB (V staged as v_norm^p, fused here)
__global__ void attn_kernel() {
    extern __shared__ float smem[];
    float* Ks = smem;
    float* Vs = smem + NS * NA;
    __shared__ float sc_p[NA], sc_invp[NA], sc_ns[NA], sc_vmin[NA], sc_us[NA];

    const int bz = blockIdx.x;
    const int b  = bz >> 6;
    const int h  = (bz >> 3) & 7;
    const int qt = bz & 7;
    const int tid = threadIdx.x;

    if (tid < NA) {
        int d = h * NA + tid;
        sc_p[tid]    = g_p[d];
        sc_invp[tid] = g_invp[d];
        sc_ns[tid]   = g_nscale[b*ND + d];
        sc_vmin[tid] = g_vmin[b*ND + d];
        sc_us[tid]   = g_unscale[b*ND + d];
    }
    __syncthreads();

    // stage K and fused v_norm^p tiles
    for (int e = tid; e < NS * 8; e += 256) {
        int s = e >> 3;
        int c = (e & 7) << 2;
        const float* kvrow = &g_kv[(size_t)(b*NS + s) * (2*ND) + h*NA];
        *(float4*)&Ks[s*NA + c] = *(const float4*)&kvrow[c];
        float4 v = *(const float4*)&kvrow[ND + c];
        float4 z;
        {
            float vn;
            vn = (v.x - sc_vmin[c+0]) * sc_ns[c+0] + B_CONSTF; z.x = __expf(sc_p[c+0] * __logf(vn));
            vn = (v.y - sc_vmin[c+1]) * sc_ns[c+1] + B_CONSTF; z.y = __expf(sc_p[c+1] * __logf(vn));
            vn = (v.z - sc_vmin[c+2]) * sc_ns[c+2] + B_CONSTF; z.z = __expf(sc_p[c+2] * __logf(vn));
            vn = (v.w - sc_vmin[c+3]) * sc_ns[c+3] + B_CONSTF; z.w = __expf(sc_p[c+3] * __logf(vn));
        }
        *(float4*)&Vs[s*NA + c] = z;
    }
    __syncthreads();

    const int ql    = tid & 63;
    const int slice = tid >> 6;
    const int qg    = qt * 64 + ql;

    unsigned long long qv2[16];
    {
        const float* qptr = &g_q[(size_t)(b*NS + qg)*ND + h*NA];
        #pragma unroll
        for (int i = 0; i < 8; i++) {
            ulonglong2 t = *(const ulonglong2*)&qptr[4*i];
            qv2[2*i] = t.x; qv2[2*i+1] = t.y;
        }
    }

    unsigned long long acc2[16];
    #pragma unroll
    for (int i = 0; i < 16; i++) acc2[i] = 0ULL;
    float l = 0.f;

    const int j0 = slice * 128;
    #pragma unroll 2
    for (int j = j0; j < j0 + 128; j++) {
        const float* kj = &Ks[j*NA];
        unsigned long long s2a = 0ULL, s2b = 0ULL;
        #pragma unroll
        for (int i = 0; i < 8; i++) {
            ulonglong2 k2 = *(const ulonglong2*)&kj[4*i];   // warp-broadcast LDS.128
            s2a = f2fma(qv2[2*i],   k2.x, s2a);
            s2b = f2fma(qv2[2*i+1], k2.y, s2b);
        }
        float a0, a1, b0, b1;
        f2unpack(s2a, a0, a1);
        f2unpack(s2b, b0, b1);
        float w = __expf(((a0 + a1) + (b0 + b1)) * SCALEF);
        l += w;
        unsigned long long w2 = f2pack(w, w);
        const float* vj = &Vs[j*NA];
        #pragma unroll
        for (int i = 0; i < 8; i++) {
            ulonglong2 v2 = *(const ulonglong2*)&vj[4*i];
            acc2[2*i]   = f2fma(w2, v2.x, acc2[2*i]);
            acc2[2*i+1] = f2fma(w2, v2.y, acc2[2*i+1]);
        }
    }
    __syncthreads();   // Ks/Vs no longer needed

    // merge 4 slices (pure addition)
    float* red = smem;                       // [4][64][33]
    float* my  = &red[(slice*64 + ql) * 33];
    my[0] = l;
    #pragma unroll
    for (int i = 0; i < 16; i++) {
        float f0, f1;
        f2unpack(acc2[i], f0, f1);
        my[1 + 2*i]     = f0;
        my[1 + 2*i + 1] = f1;
    }
    __syncthreads();

    if (tid < 64) {
        const float* r0 = &red[(0*64 + tid) * 33];
        const float* r1 = &red[(1*64 + tid) * 33];
        const float* r2 = &red[(2*64 + tid) * 33];
        const float* r3 = &red[(3*64 + tid) * 33];
        float L    = (r0[0] + r1[0]) + (r2[0] + r3[0]);
        float invL = 1.0f / L;
        int   qq   = qt * 64 + tid;
        float* outp = &g_e[(size_t)(b*NS + qq)*ND + h*NA];
        #pragma unroll
        for (int a = 0; a < NA; a++) {
            float S  = ((r0[1+a] + r1[1+a]) + (r2[1+a] + r3[1+a])) * invL;
            float ev = __expf(__logf(S) * sc_invp[a]);          // S^(1/p)
            outp[a]  = (ev - B_CONSTF) * sc_us[a] + sc_vmin[a];
        }
    }
}

// ---------------- launch ----------------
extern "C" void kernel_launch(void* const* d_in, const int* in_sizes, int n_in,
                              void* d_out, int out_size) {
    const float* context = (const float*)d_in[0];
    const float* W_Q     = (const float*)d_in[1];
    const float* W_KV    = (const float*)d_in[2];
    const float* W_out   = (const float*)d_in[3];
    const float* p_param = (const float*)d_in[4];
    float* out = (float*)d_out;

    float *pq, *pkv, *pe;
    cudaGetSymbolAddress((void**)&pq,  g_q);
    cudaGetSymbolAddress((void**)&pkv, g_kv);
    cudaGetSymbolAddress((void**)&pe,  g_e);

    // Fused Q+KV projection: W rows 0..255 -> W_Q, but they are separate tensors.
    // Launch as two column-ranges of one logical GEMM by calling twice would cost a
    // launch; instead note W_Q and W_KV are separate buffers, so run a 768-col GEMM
    // per weight source is impossible — use the split-output kernel per weight:
    //   blocks over N=256 for W_Q -> g_q,  N=512 for W_KV -> g_kv.
    gemm_f32x2_kernel<<<dim3(4, 16), 128>>>(context, W_Q,  pq,  pq,  ND, ND,   ND,    ND);
    gemm_f32x2_kernel<<<dim3(8, 16), 128>>>(context, W_KV, pkv, pkv, ND, 2*ND, 2*ND,  2*ND);

    vstats_kernel<<<NB, 1024>>>(p_param);

    cudaFuncSetAttribute(attn_kernel, cudaFuncAttributeMaxDynamicSharedMemorySize, 131072);
    attn_kernel<<<128, 256, 131072>>>();

    gemm_f32x2_kernel<<<dim3(4, 16), 128>>>(pe, W_out, out, out, ND, ND, ND, ND);
}

// round 4
// speedup vs baseline: 1.1864x; 1.1864x over previous
#include <cuda_runtime.h>
#include <math.h>

#define B_CONSTF 0.9f
#define EPSF 1e-10f
#define SCALEF 0.0625f

typedef unsigned long long ull;

// ---------------- device scratch ----------------
__device__ float g_qh[16*512*32];    // per-head Q   [bh][s][32]
__device__ float g_kh[16*512*32];    // per-head K   [bh][s][32]
__device__ float g_v [1024*256];     // V row-major  [b*s][256]
__device__ float g_vz[16*512*32];    // v_norm^p     [bh][s][32]
__device__ float g_s [16*512*512];   // exp scores   [bh][q][k]  (16.8MB)
__device__ float g_lp[16*8*512];     // row-sum partials [bh][ktile][q]
__device__ float g_pp[16*2*512*32];  // pass2 split-K partials [bh][kc][q][a]
__device__ float g_e [1024*256];     // power-mean result (row-major)
__device__ float g_vmin[512], g_nscale[512], g_unscale[512];
__device__ float g_p[256], g_invp[256];

// ---------------- f32x2 helpers ----------------
__device__ __forceinline__ ull f2pack(float lo, float hi) {
    ull r; asm("mov.b64 %0, {%1, %2};" : "=l"(r) : "f"(lo), "f"(hi)); return r;
}
__device__ __forceinline__ void f2unpack(ull v, float& lo, float& hi) {
    asm("mov.b64 {%0, %1}, %2;" : "=f"(lo), "=f"(hi) : "l"(v));
}
__device__ __forceinline__ ull f2fma(ull a, ull b, ull c) {
    ull d; asm("fma.rn.f32x2 %0, %1, %2, %3;" : "=l"(d) : "l"(a), "l"(b), "l"(c)); return d;
}

// =========================================================================
// Kernel 1: fused QKV projection.  C[1024][768] = ctx @ [W_Q; W_KV]^T
// 64x64 tiles, 256 thr, micro 4m(2 f32x2 pairs) x 4n. Epilogue scatters to
// per-head Q/K layouts and row-major V.
// smem row pad = 68 floats (272B, multiple of 16) -> all LDS.128/LDS.64 aligned.
// =========================================================================
__global__ __launch_bounds__(256) void qkv_gemm(
    const float* __restrict__ ctx, const float* __restrict__ W_Q,
    const float* __restrict__ W_KV)
{
    __shared__ float As[16][68];
    __shared__ float Bs[16][68];
    const int tid = threadIdx.x;
    const int tx = tid & 15, ty = tid >> 4;
    const int bm = blockIdx.y * 64;
    const int bn = blockIdx.x * 64;
    const float* Bsrc = (bn < 256) ? (W_Q + (size_t)bn * 256)
                                   : (W_KV + (size_t)(bn - 256) * 256);
    const int lm = tid >> 2, lc = tid & 3;

    ull acc[4][2];
    #pragma unroll
    for (int n = 0; n < 4; n++) { acc[n][0] = 0ULL; acc[n][1] = 0ULL; }

    for (int k0 = 0; k0 < 256; k0 += 16) {
        float4 a4 = *(const float4*)&ctx [(size_t)(bm + lm) * 256 + k0 + lc*4];
        As[lc*4+0][lm] = a4.x; As[lc*4+1][lm] = a4.y;
        As[lc*4+2][lm] = a4.z; As[lc*4+3][lm] = a4.w;
        float4 b4 = *(const float4*)&Bsrc[(size_t)lm * 256 + k0 + lc*4];
        Bs[lc*4+0][lm] = b4.x; Bs[lc*4+1][lm] = b4.y;
        Bs[lc*4+2][lm] = b4.z; Bs[lc*4+3][lm] = b4.w;
        __syncthreads();
        #pragma unroll
        for (int kk = 0; kk < 16; kk++) {
            ull a0 = *(const ull*)&As[kk][ty*4];
            ull a1 = *(const ull*)&As[kk][ty*4+2];
            float4 bf = *(const float4*)&Bs[kk][tx*4];
            ull b0 = f2pack(bf.x, bf.x), b1 = f2pack(bf.y, bf.y);
            ull b2 = f2pack(bf.z, bf.z), b3 = f2pack(bf.w, bf.w);
            acc[0][0] = f2fma(b0, a0, acc[0][0]); acc[0][1] = f2fma(b0, a1, acc[0][1]);
            acc[1][0] = f2fma(b1, a0, acc[1][0]); acc[1][1] = f2fma(b1, a1, acc[1][1]);
            acc[2][0] = f2fma(b2, a0, acc[2][0]); acc[2][1] = f2fma(b2, a1, acc[2][1]);
            acc[3][0] = f2fma(b3, a0, acc[3][0]); acc[3][1] = f2fma(b3, a1, acc[3][1]);
        }
        __syncthreads();
    }

    float v[4][4];
    #pragma unroll
    for (int n = 0; n < 4; n++) {
        f2unpack(acc[n][0], v[n][0], v[n][1]);
        f2unpack(acc[n][1], v[n][2], v[n][3]);
    }
    const int c = bn + tx*4;
    #pragma unroll
    for (int r = 0; r < 4; r++) {
        int row = bm + ty*4 + r;
        float4 o = make_float4(v[0][r], v[1][r], v[2][r], v[3][r]);
        int b = row >> 9, s = row & 511;
        if (c < 256) {
            int h = c >> 5, a = c & 31;
            *(float4*)&g_qh[((size_t)((b*8+h)*512 + s))*32 + a] = o;
        } else if (c < 512) {
            int kc = c - 256, h = kc >> 5, a = kc & 31;
            *(float4*)&g_kh[((size_t)((b*8+h)*512 + s))*32 + a] = o;
        } else {
            *(float4*)&g_v[(size_t)row * 256 + (c - 512)] = o;
        }
    }
}

// =========================================================================
// Kernel 2: v min/max per (b,d) + p/invp.  grid (8 dchunk, 2 b), 256 thr.
// =========================================================================
__global__ __launch_bounds__(256) void vstats_kernel(const float* __restrict__ p_param) {
    __shared__ float smn[8][32], smx[8][32];
    const int b = blockIdx.y, dc = blockIdx.x;
    const int dd = threadIdx.x & 31, sl = threadIdx.x >> 5;
    const int d = dc*32 + dd;
    float mn = 1e30f, mx = -1e30f;
    const float* base = g_v + (size_t)(b*512 + sl*64) * 256 + d;
    #pragma unroll 4
    for (int i = 0; i < 64; i++) {
        float v = base[(size_t)i * 256];
        mn = fminf(mn, v); mx = fmaxf(mx, v);
    }
    smn[sl][dd] = mn; smx[sl][dd] = mx;
    __syncthreads();
    if (sl == 0) {
        #pragma unroll
        for (int t = 1; t < 8; t++) {
            mn = fminf(mn, smn[t][dd]); mx = fmaxf(mx, smx[t][dd]);
        }
        float range = mx - mn + EPSF;
        g_vmin   [b*256 + d] = mn;
        g_nscale [b*256 + d] = (1.0f - B_CONSTF) / range;
        g_unscale[b*256 + d] = range / (1.0f - B_CONSTF);
        if (b == 0) {
            float pp = p_param[d];
            float p  = 50000.0f * tanhf(0.005f * pp) + 1.0f;
            if (p == 0.0f) p = 1e-4f;
            g_p[d] = p; g_invp[d] = 1.0f / p;
        }
    }
}

// =========================================================================
// Kernel 3: vz = v_norm^p per-head.  grid (8 schunk, 16 bh), 256 thr.
// =========================================================================
__global__ __launch_bounds__(256) void vz_kernel() {
    __shared__ float s_p[32], s_ns[32], s_vm[32];
    const int bh = blockIdx.y, sc = blockIdx.x;
    const int b = bh >> 3, h = bh & 7;
    const int tid = threadIdx.x;
    if (tid < 32) {
        int d = h*32 + tid;
        s_p[tid]  = g_p[d];
        s_ns[tid] = g_nscale[b*256 + d];
        s_vm[tid] = g_vmin[b*256 + d];
    }
    __syncthreads();
    const int a = tid & 31, sq = tid >> 5;
    #pragma unroll
    for (int it = 0; it < 8; it++) {
        int s = sc*64 + it*8 + sq;
        float v  = g_v[(size_t)(b*512 + s) * 256 + h*32 + a];
        float vn = (v - s_vm[a]) * s_ns[a] + B_CONSTF;
        g_vz[((size_t)(bh*512 + s))*32 + a] = __expf(s_p[a] * __logf(vn));
    }
}

// =========================================================================
// Kernel 4: pass1 scores.  S[bh] = exp(Q@K^T * scale), + row-sum partials.
// grid (8 kt, 8 qt, 16 bh), 256 thr, 64x64 tile, K=32 (single staging).
// =========================================================================
__global__ __launch_bounds__(256) void pass1_kernel() {
    __shared__ float As[32][68];
    __shared__ float Bs[32][68];
    const int kt = blockIdx.x, qt = blockIdx.y, bh = blockIdx.z;
    const int tid = threadIdx.x, tx = tid & 15, ty = tid >> 4;
    const float* Aq = g_qh + (size_t)bh*512*32 + (size_t)qt*64*32;
    const float* Bk = g_kh + (size_t)bh*512*32 + (size_t)kt*64*32;
    const int lm = tid >> 2, lc = tid & 3;
    {
        float4 a0 = *(const float4*)&Aq[lm*32 + lc*4];
        float4 a1 = *(const float4*)&Aq[lm*32 + 16 + lc*4];
        As[lc*4+0][lm] = a0.x; As[lc*4+1][lm] = a0.y;
        As[lc*4+2][lm] = a0.z; As[lc*4+3][lm] = a0.w;
        As[16+lc*4+0][lm] = a1.x; As[16+lc*4+1][lm] = a1.y;
        As[16+lc*4+2][lm] = a1.z; As[16+lc*4+3][lm] = a1.w;
        float4 b0 = *(const float4*)&Bk[lm*32 + lc*4];
        float4 b1 = *(const float4*)&Bk[lm*32 + 16 + lc*4];
        Bs[lc*4+0][lm] = b0.x; Bs[lc*4+1][lm] = b0.y;
        Bs[lc*4+2][lm] = b0.z; Bs[lc*4+3][lm] = b0.w;
        Bs[16+lc*4+0][lm] = b1.x; Bs[16+lc*4+1][lm] = b1.y;
        Bs[16+lc*4+2][lm] = b1.z; Bs[16+lc*4+3][lm] = b1.w;
    }
    __syncthreads();

    ull acc[4][2];
    #pragma unroll
    for (int n = 0; n < 4; n++) { acc[n][0] = 0ULL; acc[n][1] = 0ULL; }
    #pragma unroll
    for (int kk = 0; kk < 32; kk++) {
        ull a0 = *(const ull*)&As[kk][ty*4];
        ull a1 = *(const ull*)&As[kk][ty*4+2];
        float4 bf = *(const float4*)&Bs[kk][tx*4];
        ull b0 = f2pack(bf.x, bf.x), b1 = f2pack(bf.y, bf.y);
        ull b2 = f2pack(bf.z, bf.z), b3 = f2pack(bf.w, bf.w);
        acc[0][0] = f2fma(b0, a0, acc[0][0]); acc[0][1] = f2fma(b0, a1, acc[0][1]);
        acc[1][0] = f2fma(b1, a0, acc[1][0]); acc[1][1] = f2fma(b1, a1, acc[1][1]);
        acc[2][0] = f2fma(b2, a0, acc[2][0]); acc[2][1] = f2fma(b2, a1, acc[2][1]);
        acc[3][0] = f2fma(b3, a0, acc[3][0]); acc[3][1] = f2fma(b3, a1, acc[3][1]);
    }

    float w[4][4];
    #pragma unroll
    for (int n = 0; n < 4; n++) {
        f2unpack(acc[n][0], w[n][0], w[n][1]);
        f2unpack(acc[n][1], w[n][2], w[n][3]);
    }
    float rs[4] = {0.f, 0.f, 0.f, 0.f};
    #pragma unroll
    for (int n = 0; n < 4; n++)
        #pragma unroll
        for (int r = 0; r < 4; r++) {
            w[n][r] = __expf(w[n][r] * SCALEF);
            rs[r] += w[n][r];
        }
    float* Sout = g_s + (size_t)bh*512*512;
    #pragma unroll
    for (int r = 0; r < 4; r++) {
        int row = qt*64 + ty*4 + r;
        float4 o = make_float4(w[0][r], w[1][r], w[2][r], w[3][r]);
        *(float4*)&Sout[(size_t)row*512 + kt*64 + tx*4] = o;
    }
    #pragma unroll
    for (int r = 0; r < 4; r++) {
        rs[r] += __shfl_xor_sync(0xffffffffu, rs[r], 1);
        rs[r] += __shfl_xor_sync(0xffffffffu, rs[r], 2);
        rs[r] += __shfl_xor_sync(0xffffffffu, rs[r], 4);
        rs[r] += __shfl_xor_sync(0xffffffffu, rs[r], 8);
    }
    if ((tid & 15) == 0) {
        #pragma unroll
        for (int r = 0; r < 4; r++)
            g_lp[((size_t)(bh*8 + kt))*512 + qt*64 + ty*4 + r] = rs[r];
    }
}

// =========================================================================
// Kernel 5: pass2.  PP[bh][kc] = S_chunk @ Vz_chunk.  split-K2,
// grid (2 kc, 8 mt, 16 bh), 256 thr, 64x32 tile, micro 4m x 2n.
// =========================================================================
__global__ __launch_bounds__(256) void pass2_kernel() {
    __shared__ float As[16][68];
    __shared__ float Bs[16][34];
    const int kc = blockIdx.x, mt = blockIdx.y, bh = blockIdx.z;
    const int tid = threadIdx.x, tx = tid & 15, ty = tid >> 4;
    const float* Ab = g_s  + (size_t)bh*512*512 + (size_t)mt*64*512 + (size_t)kc*256;
    const float* Bb = g_vz + (size_t)bh*512*32  + (size_t)kc*256*32;
    const int lm = tid >> 2, lc = tid & 3;
    const int bkk = tid >> 4, bn2 = (tid & 15) * 2;

    ull acc[2][2];
    acc[0][0] = acc[0][1] = acc[1][0] = acc[1][1] = 0ULL;

    for (int k0 = 0; k0 < 256; k0 += 16) {
        float4 a4 = *(const float4*)&Ab[(size_t)lm*512 + k0 + lc*4];
        As[lc*4+0][lm] = a4.x; As[lc*4+1][lm] = a4.y;
        As[lc*4+2][lm] = a4.z; As[lc*4+3][lm] = a4.w;
        float2 b2 = *(const float2*)&Bb[(size_t)(k0 + bkk)*32 + bn2];
        *(float2*)&Bs[bkk][bn2] = b2;
        __syncthreads();
        #pragma unroll
        for (int kk = 0; kk < 16; kk++) {
            ull a0 = *(const ull*)&As[kk][ty*4];
            ull a1 = *(const ull*)&As[kk][ty*4+2];
            float2 bf = *(const float2*)&Bs[kk][tx*2];
            ull b0 = f2pack(bf.x, bf.x), b1 = f2pack(bf.y, bf.y);
            acc[0][0] = f2fma(b0, a0, acc[0][0]); acc[0][1] = f2fma(b0, a1, acc[0][1]);
            acc[1][0] = f2fma(b1, a0, acc[1][0]); acc[1][1] = f2fma(b1, a1, acc[1][1]);
        }
        __syncthreads();
    }
    float v[2][4];
    f2unpack(acc[0][0], v[0][0], v[0][1]); f2unpack(acc[0][1], v[0][2], v[0][3]);
    f2unpack(acc[1][0], v[1][0], v[1][1]); f2unpack(acc[1][1], v[1][2], v[1][3]);
    float* Pp = g_pp + ((size_t)(bh*2 + kc)*512 + mt*64)*32;
    #pragma unroll
    for (int r = 0; r < 4; r++) {
        float2 o = make_float2(v[0][r], v[1][r]);
        *(float2*)&Pp[(ty*4 + r)*32 + tx*2] = o;
    }
}

// =========================================================================
// Kernel 6: merge partials, power-mean epilogue -> g_e (row-major).
// grid (8 qchunk, 16 bh), 256 thr.
// =========================================================================
__global__ __launch_bounds__(256) void merge_kernel() {
    __shared__ float sinvL[64];
    __shared__ float s_invp[32], s_us[32], s_vm[32];
    const int bh = blockIdx.y, qb = blockIdx.x * 64;
    const int b = bh >> 3, h = bh & 7;
    const int tid = threadIdx.x;
    if (tid < 32) {
        int d = h*32 + tid;
        s_invp[tid] = g_invp[d];
        s_us[tid]   = g_unscale[b*256 + d];
        s_vm[tid]   = g_vmin[b*256 + d];
    }
    if (tid < 64) {
        int q = qb + tid;
        float L = 0.f;
        #pragma unroll
        for (int kt = 0; kt < 8; kt++) L += g_lp[((size_t)(bh*8 + kt))*512 + q];
        sinvL[tid] = 1.0f / L;
    }
    __syncthreads();
    const int a = tid & 31, qq = tid >> 5;
    #pragma unroll
    for (int it = 0; it < 8; it++) {
        int ql = it*8 + qq;
        int q  = qb + ql;
        float v0 = g_pp[((size_t)(bh*2 + 0)*512 + q)*32 + a];
        float v1 = g_pp[((size_t)(bh*2 + 1)*512 + q)*32 + a];
        float S  = (v0 + v1) * sinvL[ql];
        float ev = __expf(__logf(S) * s_invp[a]);
        g_e[(size_t)(b*512 + q)*256 + h*32 + a] = (ev - B_CONSTF) * s_us[a] + s_vm[a];
    }
}

// =========================================================================
// Kernel 7: output projection.  out[1024][256] = g_e @ W_out^T.
// grid (8 nt(32), 16 mt(64)), 256 thr, micro 4m x 2n.
// =========================================================================
__global__ __launch_bounds__(256) void out_gemm(const float* __restrict__ Wo,
                                                float* __restrict__ out) {
    __shared__ float As[16][68];
    __shared__ float Bs[16][34];
    const int bn = blockIdx.x * 32;
    const int bm = blockIdx.y * 64;
    const int tid = threadIdx.x, tx = tid & 15, ty = tid >> 4;
    const int lm = tid >> 2, lc = tid & 3;
    const int ln = tid & 31, lk = tid >> 5;   // B fill (tid<128)

    ull acc[2][2];
    acc[0][0] = acc[0][1] = acc[1][0] = acc[1][1] = 0ULL;

    for (int k0 = 0; k0 < 256; k0 += 16) {
        float4 a4 = *(const float4*)&g_e[(size_t)(bm + lm)*256 + k0 + lc*4];
        As[lc*4+0][lm] = a4.x; As[lc*4+1][lm] = a4.y;
        As[lc*4+2][lm] = a4.z; As[lc*4+3][lm] = a4.w;
        if (tid < 128) {
            float4 w4 = *(const float4*)&Wo[(size_t)(bn + ln)*256 + k0 + lk*4];
            Bs[lk*4+0][ln] = w4.x; Bs[lk*4+1][ln] = w4.y;
            Bs[lk*4+2][ln] = w4.z; Bs[lk*4+3][ln] = w4.w;
        }
        __syncthreads();
        #pragma unroll
        for (int kk = 0; kk < 16; kk++) {
            ull a0 = *(const ull*)&As[kk][ty*4];
            ull a1 = *(const ull*)&As[kk][ty*4+2];
            float2 bf = *(const float2*)&Bs[kk][tx*2];
            ull b0 = f2pack(bf.x, bf.x), b1 = f2pack(bf.y, bf.y);
            acc[0][0] = f2fma(b0, a0, acc[0][0]); acc[0][1] = f2fma(b0, a1, acc[0][1]);
            acc[1][0] = f2fma(b1, a0, acc[1][0]); acc[1][1] = f2fma(b1, a1, acc[1][1]);
        }
        __syncthreads();
    }
    float v[2][4];
    f2unpack(acc[0][0], v[0][0], v[0][1]); f2unpack(acc[0][1], v[0][2], v[0][3]);
    f2unpack(acc[1][0], v[1][0], v[1][1]); f2unpack(acc[1][1], v[1][2], v[1][3]);
    #pragma unroll
    for (int r = 0; r < 4; r++) {
        float2 o = make_float2(v[0][r], v[1][r]);
        *(float2*)&out[(size_t)(bm + ty*4 + r)*256 + bn + tx*2] = o;
    }
}

// ---------------- launch ----------------
extern "C" void kernel_launch(void* const* d_in, const int* in_sizes, int n_in,
                              void* d_out, int out_size) {
    const float* context = (const float*)d_in[0];
    const float* W_Q     = (const float*)d_in[1];
    const float* W_KV    = (const float*)d_in[2];
    const float* W_out   = (const float*)d_in[3];
    const float* p_param = (const float*)d_in[4];
    float* out = (float*)d_out;

    qkv_gemm   <<<dim3(12, 16),    256>>>(context, W_Q, W_KV);
    vstats_kernel<<<dim3(8, 2),    256>>>(p_param);
    vz_kernel  <<<dim3(8, 16),     256>>>();
    pass1_kernel<<<dim3(8, 8, 16), 256>>>();
    pass2_kernel<<<dim3(2, 8, 16), 256>>>();
    merge_kernel<<<dim3(8, 16),    256>>>();
    out_gemm   <<<dim3(8, 16),     256>>>(W_out, out);
}